// round 12
// baseline (speedup 1.0000x reference)
#include <cuda_runtime.h>
#include <cuda_bf16.h>
#include <cstdint>

#define B_T    16000
#define D_IN   320
#define E_DIM  16
#define K_CB   8192
#define ROWS_PB 128
#define GRID_R (B_T / ROWS_PB)     // 125 blocks, each owns 128 rows x all cands
#define TC     128                 // cands per smem tile
#define NTILE  (K_CB / TC)         // 64
#define DELTA  4e-5f               // >= 2.3x the ~1.7e-5 certified 2-eps bound

// ---- scratch (device globals: the sanctioned no-alloc path) ----
__device__ __align__(16) unsigned short g_Ak[B_T * 64];   // [v1,v2,v1,0] x16 bf16, 2 MB
__device__ __align__(16) unsigned short g_Bk[K_CB * 64];  // [c1,c1,c2,0] x16 bf16, 1 MB
__device__ __align__(16) float g_V[B_T * E_DIM];          // raw fp32 rows, 1 MB
__device__ int g_dirty_n;
__device__ int g_dirty[B_T];

// ---------------------------------------------------------------------------
__device__ __forceinline__ uint32_t smem_u32(const void* p) {
    uint32_t a;
    asm("{ .reg .u64 t; cvta.to.shared.u64 t, %1; cvt.u32.u64 %0, t; }" : "=r"(a) : "l"(p));
    return a;
}
__device__ __forceinline__ void cpasync16(uint32_t dst, const void* src) {
    asm volatile("cp.async.cg.shared.global [%0], [%1], 16;" :: "r"(dst), "l"(src));
}
__device__ __forceinline__ void cp_commit() {
    asm volatile("cp.async.commit_group;" ::: "memory");
}
__device__ __forceinline__ void cp_wait0() {
    asm volatile("cp.async.wait_group 0;" ::: "memory");
}
__device__ __forceinline__ uint32_t lds32(uint32_t a) {
    uint32_t v; asm volatile("ld.shared.b32 %0, [%1];" : "=r"(v) : "r"(a)); return v;
}
__device__ __forceinline__ void mma16816(float* d, const uint32_t* a, uint32_t b0, uint32_t b1) {
    asm volatile(
        "mma.sync.aligned.m16n8k16.row.col.f32.bf16.bf16.f32 "
        "{%0,%1,%2,%3}, {%4,%5,%6,%7}, {%8,%9}, {%0,%1,%2,%3};"
        : "+f"(d[0]), "+f"(d[1]), "+f"(d[2]), "+f"(d[3])
        : "r"(a[0]), "r"(a[1]), "r"(a[2]), "r"(a[3]), "r"(b0), "r"(b1));
}

// ---- order-preserving key helpers (alu-pipe ops only) ----
__device__ __forceinline__ unsigned long long mk_key(float v, uint32_t rk) {
    uint32_t u  = __float_as_uint(v);
    uint32_t ou = u ^ ((uint32_t)((int32_t)u >> 31) | 0x80000000u);
    return ((unsigned long long)ou << 32) | rk;     // lexicographic: score, then lower k
}
__device__ __forceinline__ void upd(unsigned long long& best, unsigned long long& sec,
                                    float v, uint32_t rk) {
    unsigned long long key = mk_key(v, rk);
    unsigned long long mn  = key < best ? key : best;
    if (key > best) best = key;
    if (mn  > sec)  sec  = mn;
}
__device__ __forceinline__ float key_score(unsigned long long k) {
    uint32_t hi = (uint32_t)(k >> 32);
    uint32_t u  = (hi & 0x80000000u) ? (hi ^ 0x80000000u) : ~hi;
    return __uint_as_float(u);
}
__device__ __forceinline__ int key_idx(unsigned long long k) {
    return 8191 - (int)(uint32_t)k;
}

// ============================================================================
// Kernel 1: projection (fp32, warp-per-row).  Writes raw fp32 g_V AND the
// 2.5-digit NORMALIZED bf16 split g_Ak = [v1, v2, v1, 0] (v-hat = v/||v||2).
// ============================================================================
#define PS_STR 17
__global__ __launch_bounds__(256) void proj_split_kernel(const float* __restrict__ H,
                                                         const float* __restrict__ P) {
    __shared__ float Ps[D_IN * PS_STR];
    const int tid = threadIdx.x;
    for (int i = tid; i < D_IN * E_DIM; i += 256) {
        int d = i >> 4, e = i & 15;
        Ps[d * PS_STR + e] = P[i];
    }
    __syncthreads();

    const int warp = tid >> 5;
    const int lane = tid & 31;
    const int row  = blockIdx.x * 8 + warp;

    float acc[E_DIM];
#pragma unroll
    for (int e = 0; e < E_DIM; ++e) acc[e] = 0.0f;

    const float* h = H + (size_t)row * D_IN;
#pragma unroll
    for (int i = 0; i < 10; ++i) {
        float hv = h[i * 32 + lane];
        const float* p = &Ps[(i * 32 + lane) * PS_STR];
#pragma unroll
        for (int e = 0; e < E_DIM; ++e) acc[e] = fmaf(hv, p[e], acc[e]);
    }
#pragma unroll
    for (int off = 16; off >= 1; off >>= 1)
#pragma unroll
        for (int e = 0; e < E_DIM; ++e)
            acc[e] += __shfl_xor_sync(0xFFFFFFFFu, acc[e], off);

    if (lane < E_DIM) {
        float n2 = 0.0f;
#pragma unroll
        for (int e = 0; e < E_DIM; ++e) n2 = fmaf(acc[e], acc[e], n2);
        float inv = rsqrtf(fmaxf(n2, 1e-30f));

        g_V[(size_t)row * E_DIM + lane] = acc[lane];

        float vh = acc[lane] * inv;
        __nv_bfloat16 b1 = __float2bfloat16(vh);
        float r1 = vh - __bfloat162float(b1);
        __nv_bfloat16 b2 = __float2bfloat16(r1);
        unsigned short* dst = g_Ak + (size_t)row * 64;
        dst[lane]      = __bfloat16_as_ushort(b1);
        dst[16 + lane] = __bfloat16_as_ushort(b2);
        dst[32 + lane] = __bfloat16_as_ushort(b1);
        dst[48 + lane] = 0;
    }
}

// ============================================================================
// Kernel 2: codebook 2-digit bf16 split [c1, c1, c2, 0]; resets dirty counter.
// ============================================================================
__global__ __launch_bounds__(256) void cb_split_kernel(const float* __restrict__ CB) {
    if (blockIdx.x == 0 && threadIdx.x == 0) g_dirty_n = 0;
    int r = blockIdx.x * 256 + threadIdx.x;
    if (r >= K_CB) return;
    unsigned short* dst = g_Bk + (size_t)r * 64;
#pragma unroll
    for (int e = 0; e < E_DIM; ++e) {
        float v = CB[(size_t)r * E_DIM + e];
        __nv_bfloat16 c1 = __float2bfloat16(v);
        float r1 = v - __bfloat162float(c1);
        __nv_bfloat16 c2 = __float2bfloat16(r1);
        dst[e]      = __bfloat16_as_ushort(c1);
        dst[16 + e] = __bfloat16_as_ushort(c1);
        dst[32 + e] = __bfloat16_as_ushort(c2);
        dst[48 + e] = 0;
    }
}

// ============================================================================
// Kernel 3: approx HMMA score (K=48) + u64-key (best, second) tracking.
// grid 125, block 256 (8 warps x 16 rows).  Clean rows (gap >= DELTA) write
// their label; near-tie rows go to the dirty list.  Keys live on the alu pipe.
// ============================================================================
#define SM_A  0
#define SM_B0 16384
#define SM_B1 32768

__global__ __launch_bounds__(256) void score_kernel(float* __restrict__ out) {
    __shared__ __align__(16) char smem[49152];
    const uint32_t sb = smem_u32(smem);
    const int tid  = threadIdx.x;
    const int lane = tid & 31;
    const int warp = tid >> 5;
    const int rb   = blockIdx.x * ROWS_PB;
    const int q    = lane >> 2;
    const int c4   = lane & 3;

    // stage A (128 rows x 128B, unit-swizzled) and B tile 0
#pragma unroll
    for (int i = 0; i < 4; ++i) {
        int idx = tid + i * 256;
        int row = idx >> 3, u = idx & 7;
        cpasync16(sb + SM_A + row * 128 + ((u ^ (row & 7)) << 4),
                  (const char*)g_Ak + (size_t)(rb + row) * 128 + u * 16);
    }
#pragma unroll
    for (int i = 0; i < 4; ++i) {
        int idx = tid + i * 256;
        int row = idx >> 3, u = idx & 7;
        cpasync16(sb + SM_B0 + row * 128 + ((u ^ (row & 7)) << 4),
                  (const char*)g_Bk + (size_t)row * 128 + u * 16);
    }
    cp_commit();
    cp_wait0();
    __syncthreads();

    // A fragments (validated mapping): rows R0 = warp*16+q, R1 = R0+8
    uint32_t a[3][4];
    {
        int R0 = warp * 16 + q, R1 = R0 + 8;
        uint32_t base0 = sb + SM_A + R0 * 128 + c4 * 4;
        uint32_t base1 = sb + SM_A + R1 * 128 + c4 * 4;
        int x0 = R0 & 7, x1 = R1 & 7;
#pragma unroll
        for (int kk = 0; kk < 3; ++kk) {
            a[kk][0] = lds32(base0 + (((2 * kk)     ^ x0) << 4));
            a[kk][1] = lds32(base1 + (((2 * kk)     ^ x1) << 4));
            a[kk][2] = lds32(base0 + (((2 * kk + 1) ^ x0) << 4));
            a[kk][3] = lds32(base1 + (((2 * kk + 1) ^ x1) << 4));
        }
    }

    unsigned long long b0k = 0ull, s0k = 0ull;   // slot 0: row R0
    unsigned long long b1k = 0ull, s1k = 0ull;   // slot 1: row R1

    for (int t = 0; t < NTILE; ++t) {
        cp_wait0();
        __syncthreads();
        const uint32_t buf = sb + ((t & 1) ? SM_B1 : SM_B0);
        if (t + 1 < NTILE) {
            const uint32_t nb = sb + (((t + 1) & 1) ? SM_B1 : SM_B0);
            int cand0 = (t + 1) * TC;
#pragma unroll
            for (int i = 0; i < 4; ++i) {
                int idx = tid + i * 256;
                int row = idx >> 3, u = idx & 7;
                cpasync16(nb + row * 128 + ((u ^ (row & 7)) << 4),
                          (const char*)g_Bk + (size_t)(cand0 + row) * 128 + u * 16);
            }
            cp_commit();
        }

        // 16 n-groups, processed in pairs (2 independent HMMA chains)
#pragma unroll 2
        for (int gg = 0; gg < 8; ++gg) {
            const int g0 = 2 * gg, g1 = 2 * gg + 1;
            float d0[4] = {0.f, 0.f, 0.f, 0.f};
            float d1[4] = {0.f, 0.f, 0.f, 0.f};
            uint32_t cb0 = buf + (g0 * 8 + q) * 128 + c4 * 4;
            uint32_t cb1 = buf + (g1 * 8 + q) * 128 + c4 * 4;
#pragma unroll
            for (int kk = 0; kk < 3; ++kk) {
                uint32_t o0 = ((2 * kk)     ^ q) << 4;
                uint32_t o1 = ((2 * kk + 1) ^ q) << 4;
                uint32_t b00 = lds32(cb0 + o0), b01 = lds32(cb0 + o1);
                uint32_t b10 = lds32(cb1 + o0), b11 = lds32(cb1 + o1);
                mma16816(d0, a[kk], b00, b01);
                mma16816(d1, a[kk], b10, b11);
            }
            // cands: k0, k0+1 (chain g0) and k0+8, k0+9 (chain g1)
            const int k0 = t * TC + g0 * 8 + 2 * c4;
            const uint32_t rk0 = (uint32_t)(8191 - k0);
            upd(b0k, s0k, d0[0], rk0);
            upd(b0k, s0k, d0[1], rk0 - 1);
            upd(b0k, s0k, d1[0], rk0 - 8);
            upd(b0k, s0k, d1[1], rk0 - 9);
            upd(b1k, s1k, d0[2], rk0);
            upd(b1k, s1k, d0[3], rk0 - 1);
            upd(b1k, s1k, d1[2], rk0 - 8);
            upd(b1k, s1k, d1[3], rk0 - 9);
        }
        __syncthreads();
    }

    // quad merge (lanes c4=0..3 hold disjoint cand residues of the same rows)
#pragma unroll
    for (int off = 1; off <= 2; off <<= 1) {
        unsigned long long ob = __shfl_xor_sync(0xFFFFFFFFu, b0k, off);
        unsigned long long os = __shfl_xor_sync(0xFFFFFFFFu, s0k, off);
        unsigned long long mn = b0k < ob ? b0k : ob;
        unsigned long long mx = s0k > os ? s0k : os;
        s0k = mn > mx ? mn : mx;
        b0k = b0k > ob ? b0k : ob;
        ob = __shfl_xor_sync(0xFFFFFFFFu, b1k, off);
        os = __shfl_xor_sync(0xFFFFFFFFu, s1k, off);
        mn = b1k < ob ? b1k : ob;
        mx = s1k > os ? s1k : os;
        s1k = mn > mx ? mn : mx;
        b1k = b1k > ob ? b1k : ob;
    }

    if (c4 == 0) {
        int r0 = rb + warp * 16 + q;
        if (key_score(b0k) - key_score(s0k) >= DELTA) out[r0] = (float)key_idx(b0k);
        else { int ix = atomicAdd(&g_dirty_n, 1); g_dirty[ix] = r0; }
        int r1 = r0 + 8;
        if (key_score(b1k) - key_score(s1k) >= DELTA) out[r1] = (float)key_idx(b1k);
        else { int ix = atomicAdd(&g_dirty_n, 1); g_dirty[ix] = r1; }
    }
}

// ============================================================================
// Kernel 4: exact fp32 rescore of dirty rows (expected ~0.07%), NO atomics:
// per-thread local u64 key max -> warp shfl reduce -> smem -> single write.
// ============================================================================
__global__ __launch_bounds__(256) void cleanup_kernel(const float* __restrict__ CB,
                                                      float* __restrict__ out) {
    __shared__ float vrow[E_DIM];
    __shared__ unsigned long long wred[8];
    const int n = g_dirty_n;
    for (int i = blockIdx.x; i < n; i += gridDim.x) {
        const int row = g_dirty[i];
        if (threadIdx.x < E_DIM) vrow[threadIdx.x] = g_V[(size_t)row * E_DIM + threadIdx.x];
        __syncthreads();
        float v[E_DIM];
#pragma unroll
        for (int e = 0; e < E_DIM; ++e) v[e] = vrow[e];

        unsigned long long best = 0ull;
        for (int c = threadIdx.x; c < K_CB; c += 256) {
            const float4* cb = (const float4*)(CB + (size_t)c * E_DIM);
            float4 a = cb[0], b = cb[1], cc = cb[2], d = cb[3];
            float t0 = a.x * v[0], t1 = a.y * v[1];
            t0 = fmaf(a.z, v[2],  t0); t1 = fmaf(a.w, v[3],  t1);
            t0 = fmaf(b.x, v[4],  t0); t1 = fmaf(b.y, v[5],  t1);
            t0 = fmaf(b.z, v[6],  t0); t1 = fmaf(b.w, v[7],  t1);
            t0 = fmaf(cc.x, v[8],  t0); t1 = fmaf(cc.y, v[9],  t1);
            t0 = fmaf(cc.z, v[10], t0); t1 = fmaf(cc.w, v[11], t1);
            t0 = fmaf(d.x, v[12], t0); t1 = fmaf(d.y, v[13], t1);
            t0 = fmaf(d.z, v[14], t0); t1 = fmaf(d.w, v[15], t1);
            unsigned long long key = mk_key(t0 + t1, (uint32_t)(8191 - c));
            if (key > best) best = key;
        }
#pragma unroll
        for (int off = 16; off >= 1; off >>= 1) {
            unsigned long long ob = __shfl_xor_sync(0xFFFFFFFFu, best, off);
            if (ob > best) best = ob;
        }
        if ((threadIdx.x & 31) == 0) wred[threadIdx.x >> 5] = best;
        __syncthreads();
        if (threadIdx.x == 0) {
            unsigned long long b = wred[0];
#pragma unroll
            for (int w = 1; w < 8; ++w) if (wred[w] > b) b = wred[w];
            out[row] = (float)key_idx(b);
        }
        __syncthreads();
    }
}

// ============================================================================
extern "C" void kernel_launch(void* const* d_in, const int* in_sizes, int n_in,
                              void* d_out, int out_size) {
    // Input dispatch by element count (ordering-proof):
    //   H = 5,120,000 ; P = 5,120 ; CB = 131,072
    const float* H  = nullptr;
    const float* P  = nullptr;
    const float* CB = nullptr;
    for (int i = 0; i < n_in; ++i) {
        if      (in_sizes[i] == B_T * D_IN)   H  = (const float*)d_in[i];
        else if (in_sizes[i] == D_IN * E_DIM) P  = (const float*)d_in[i];
        else if (in_sizes[i] == K_CB * E_DIM) CB = (const float*)d_in[i];
    }
    if (!H)  H  = (const float*)d_in[0];
    if (!P)  P  = (const float*)d_in[1];
    if (!CB) CB = (const float*)d_in[2];

    float* out = (float*)d_out;   // labels as float VALUES (float32 output buffer)

    proj_split_kernel<<<B_T / 8, 256>>>(H, P);
    cb_split_kernel<<<(K_CB + 255) / 256, 256>>>(CB);
    score_kernel<<<GRID_R, 256>>>(out);
    cleanup_kernel<<<128, 256>>>(CB, out);
}

// round 13
// speedup vs baseline: 1.8229x; 1.8229x over previous
#include <cuda_runtime.h>
#include <cuda_bf16.h>
#include <cstdint>

#define B_T    16000
#define D_IN   320
#define E_DIM  16
#define K_CB   8192
#define ROWS_PB 128
#define GRID_R (B_T / ROWS_PB)     // 125 row-groups
#define KSP    8                   // k-splits -> 1000 blocks
#define CANDS  (K_CB / KSP)        // 1024 cands per block
#define TC     128                 // cands per smem tile
#define NTILE  (CANDS / TC)        // 8
#define DELTA  2e-4f               // round-11 validated margin (>=2.6x err bound)

// ---- scratch (device globals: the sanctioned no-alloc path) ----
__device__ __align__(16) unsigned short g_Ak[B_T * 64];   // [v1,v2,v1,0] x16 bf16, 2 MB
__device__ __align__(16) unsigned short g_Bk[K_CB * 64];  // [c1,c1,c2,0] x16 bf16, 1 MB
__device__ __align__(16) float g_V[B_T * E_DIM];          // raw fp32 rows, 1 MB
__device__ float g_pb[KSP * B_T];                          // per-kseg best
__device__ float g_ps[KSP * B_T];                          // per-kseg second
__device__ int   g_px[KSP * B_T];                          // per-kseg argbest
__device__ int g_dirty_n;
__device__ int g_dirty[B_T];

// ---------------------------------------------------------------------------
__device__ __forceinline__ uint32_t smem_u32(const void* p) {
    uint32_t a;
    asm("{ .reg .u64 t; cvta.to.shared.u64 t, %1; cvt.u32.u64 %0, t; }" : "=r"(a) : "l"(p));
    return a;
}
__device__ __forceinline__ void cpasync16(uint32_t dst, const void* src) {
    asm volatile("cp.async.cg.shared.global [%0], [%1], 16;" :: "r"(dst), "l"(src));
}
__device__ __forceinline__ void cp_commit() {
    asm volatile("cp.async.commit_group;" ::: "memory");
}
__device__ __forceinline__ void cp_wait0() {
    asm volatile("cp.async.wait_group 0;" ::: "memory");
}
__device__ __forceinline__ uint32_t lds32(uint32_t a) {
    uint32_t v; asm volatile("ld.shared.b32 %0, [%1];" : "=r"(v) : "r"(a)); return v;
}
__device__ __forceinline__ void mma16816(float* d, const uint32_t* a, uint32_t b0, uint32_t b1) {
    asm volatile(
        "mma.sync.aligned.m16n8k16.row.col.f32.bf16.bf16.f32 "
        "{%0,%1,%2,%3}, {%4,%5,%6,%7}, {%8,%9}, {%0,%1,%2,%3};"
        : "+f"(d[0]), "+f"(d[1]), "+f"(d[2]), "+f"(d[3])
        : "r"(a[0]), "r"(a[1]), "r"(a[2]), "r"(a[3]), "r"(b0), "r"(b1));
}

// ============================================================================
// Kernel 1: projection (fp32, warp-per-row).  Writes raw fp32 g_V AND the
// 2.5-digit NORMALIZED bf16 split g_Ak = [v1, v2, v1, 0] (v-hat = v/||v||2).
// ============================================================================
#define PS_STR 17
__global__ __launch_bounds__(256) void proj_split_kernel(const float* __restrict__ H,
                                                         const float* __restrict__ P) {
    __shared__ float Ps[D_IN * PS_STR];
    const int tid = threadIdx.x;
    for (int i = tid; i < D_IN * E_DIM; i += 256) {
        int d = i >> 4, e = i & 15;
        Ps[d * PS_STR + e] = P[i];
    }
    __syncthreads();

    const int warp = tid >> 5;
    const int lane = tid & 31;
    const int row  = blockIdx.x * 8 + warp;

    float acc[E_DIM];
#pragma unroll
    for (int e = 0; e < E_DIM; ++e) acc[e] = 0.0f;

    const float* h = H + (size_t)row * D_IN;
#pragma unroll
    for (int i = 0; i < 10; ++i) {
        float hv = h[i * 32 + lane];
        const float* p = &Ps[(i * 32 + lane) * PS_STR];
#pragma unroll
        for (int e = 0; e < E_DIM; ++e) acc[e] = fmaf(hv, p[e], acc[e]);
    }
#pragma unroll
    for (int off = 16; off >= 1; off >>= 1)
#pragma unroll
        for (int e = 0; e < E_DIM; ++e)
            acc[e] += __shfl_xor_sync(0xFFFFFFFFu, acc[e], off);

    if (lane < E_DIM) {
        float n2 = 0.0f;
#pragma unroll
        for (int e = 0; e < E_DIM; ++e) n2 = fmaf(acc[e], acc[e], n2);
        float inv = rsqrtf(fmaxf(n2, 1e-30f));

        g_V[(size_t)row * E_DIM + lane] = acc[lane];

        float vh = acc[lane] * inv;
        __nv_bfloat16 b1 = __float2bfloat16(vh);
        float r1 = vh - __bfloat162float(b1);
        __nv_bfloat16 b2 = __float2bfloat16(r1);
        unsigned short* dst = g_Ak + (size_t)row * 64;
        dst[lane]      = __bfloat16_as_ushort(b1);
        dst[16 + lane] = __bfloat16_as_ushort(b2);
        dst[32 + lane] = __bfloat16_as_ushort(b1);
        dst[48 + lane] = 0;
    }
}

// ============================================================================
// Kernel 2: codebook 2-digit bf16 split [c1, c1, c2, 0]; resets dirty counter.
// ============================================================================
__global__ __launch_bounds__(256) void cb_split_kernel(const float* __restrict__ CB) {
    if (blockIdx.x == 0 && threadIdx.x == 0) g_dirty_n = 0;
    int r = blockIdx.x * 256 + threadIdx.x;
    if (r >= K_CB) return;
    unsigned short* dst = g_Bk + (size_t)r * 64;
#pragma unroll
    for (int e = 0; e < E_DIM; ++e) {
        float v = CB[(size_t)r * E_DIM + e];
        __nv_bfloat16 c1 = __float2bfloat16(v);
        float r1 = v - __bfloat162float(c1);
        __nv_bfloat16 c2 = __float2bfloat16(r1);
        dst[e]      = __bfloat16_as_ushort(c1);
        dst[16 + e] = __bfloat16_as_ushort(c1);
        dst[32 + e] = __bfloat16_as_ushort(c2);
        dst[48 + e] = 0;
    }
}

// ============================================================================
// Kernel 3: approx HMMA score (K=48), k-split 8 ways -> grid (125, 8) = 1000
// blocks (round-12's grid-125 single-wave imbalance fixed).  Round-11 float
// (best, second) epilogue (u64 keys reverted).  Writes per-kseg partials.
// ============================================================================
#define SM_A  0
#define SM_B0 16384
#define SM_B1 32768

__global__ __launch_bounds__(256) void score_kernel() {
    __shared__ __align__(16) char smem[49152];
    const uint32_t sb = smem_u32(smem);
    const int tid  = threadIdx.x;
    const int lane = tid & 31;
    const int warp = tid >> 5;
    const int rb   = blockIdx.x * ROWS_PB;
    const int kseg = blockIdx.y;
    const int kb0  = kseg * CANDS;
    const int q    = lane >> 2;
    const int c4   = lane & 3;

    // stage A (128 rows x 128B, unit-swizzled) and B tile 0
#pragma unroll
    for (int i = 0; i < 4; ++i) {
        int idx = tid + i * 256;
        int row = idx >> 3, u = idx & 7;
        cpasync16(sb + SM_A + row * 128 + ((u ^ (row & 7)) << 4),
                  (const char*)g_Ak + (size_t)(rb + row) * 128 + u * 16);
    }
#pragma unroll
    for (int i = 0; i < 4; ++i) {
        int idx = tid + i * 256;
        int row = idx >> 3, u = idx & 7;
        cpasync16(sb + SM_B0 + row * 128 + ((u ^ (row & 7)) << 4),
                  (const char*)g_Bk + (size_t)(kb0 + row) * 128 + u * 16);
    }
    cp_commit();
    cp_wait0();
    __syncthreads();

    // A fragments (validated mapping): rows R0 = warp*16+q, R1 = R0+8
    uint32_t a[3][4];
    {
        int R0 = warp * 16 + q, R1 = R0 + 8;
        uint32_t base0 = sb + SM_A + R0 * 128 + c4 * 4;
        uint32_t base1 = sb + SM_A + R1 * 128 + c4 * 4;
        int x0 = R0 & 7, x1 = R1 & 7;
#pragma unroll
        for (int kk = 0; kk < 3; ++kk) {
            a[kk][0] = lds32(base0 + (((2 * kk)     ^ x0) << 4));
            a[kk][1] = lds32(base1 + (((2 * kk)     ^ x1) << 4));
            a[kk][2] = lds32(base0 + (((2 * kk + 1) ^ x0) << 4));
            a[kk][3] = lds32(base1 + (((2 * kk + 1) ^ x1) << 4));
        }
    }

    float best0 = __int_as_float(0xff800000), sec0 = best0;
    float best1 = __int_as_float(0xff800000), sec1 = best1;
    int bi0 = 0, bi1 = 0;

    for (int t = 0; t < NTILE; ++t) {
        cp_wait0();
        __syncthreads();
        const uint32_t buf = sb + ((t & 1) ? SM_B1 : SM_B0);
        if (t + 1 < NTILE) {
            const uint32_t nb = sb + (((t + 1) & 1) ? SM_B1 : SM_B0);
            int cand0 = kb0 + (t + 1) * TC;
#pragma unroll
            for (int i = 0; i < 4; ++i) {
                int idx = tid + i * 256;
                int row = idx >> 3, u = idx & 7;
                cpasync16(nb + row * 128 + ((u ^ (row & 7)) << 4),
                          (const char*)g_Bk + (size_t)(cand0 + row) * 128 + u * 16);
            }
            cp_commit();
        }

        // 16 n-groups, processed in pairs (2 independent HMMA chains)
#pragma unroll 2
        for (int gg = 0; gg < 8; ++gg) {
            const int g0 = 2 * gg, g1 = 2 * gg + 1;
            float d0[4] = {0.f, 0.f, 0.f, 0.f};
            float d1[4] = {0.f, 0.f, 0.f, 0.f};
            uint32_t cb0 = buf + (g0 * 8 + q) * 128 + c4 * 4;
            uint32_t cb1 = buf + (g1 * 8 + q) * 128 + c4 * 4;
#pragma unroll
            for (int kk = 0; kk < 3; ++kk) {
                uint32_t o0 = ((2 * kk)     ^ q) << 4;
                uint32_t o1 = ((2 * kk + 1) ^ q) << 4;
                uint32_t b00 = lds32(cb0 + o0), b01 = lds32(cb0 + o1);
                uint32_t b10 = lds32(cb1 + o0), b11 = lds32(cb1 + o1);
                mma16816(d0, a[kk], b00, b01);
                mma16816(d1, a[kk], b10, b11);
            }
            const int k0 = kb0 + t * TC + g0 * 8 + 2 * c4;    // g1 cands = k0+8,+9
            // ascending k, strict > = first-max (round-11 proven epilogue)
            if (d0[0] > best0) { sec0 = best0; best0 = d0[0]; bi0 = k0; }     else sec0 = fmaxf(sec0, d0[0]);
            if (d0[1] > best0) { sec0 = best0; best0 = d0[1]; bi0 = k0 + 1; } else sec0 = fmaxf(sec0, d0[1]);
            if (d1[0] > best0) { sec0 = best0; best0 = d1[0]; bi0 = k0 + 8; } else sec0 = fmaxf(sec0, d1[0]);
            if (d1[1] > best0) { sec0 = best0; best0 = d1[1]; bi0 = k0 + 9; } else sec0 = fmaxf(sec0, d1[1]);
            if (d0[2] > best1) { sec1 = best1; best1 = d0[2]; bi1 = k0; }     else sec1 = fmaxf(sec1, d0[2]);
            if (d0[3] > best1) { sec1 = best1; best1 = d0[3]; bi1 = k0 + 1; } else sec1 = fmaxf(sec1, d0[3]);
            if (d1[2] > best1) { sec1 = best1; best1 = d1[2]; bi1 = k0 + 8; } else sec1 = fmaxf(sec1, d1[2]);
            if (d1[3] > best1) { sec1 = best1; best1 = d1[3]; bi1 = k0 + 9; } else sec1 = fmaxf(sec1, d1[3]);
        }
        __syncthreads();
    }

    // quad merge (lanes c4=0..3 hold disjoint cand residues of the same rows)
#pragma unroll
    for (int off = 1; off <= 2; off <<= 1) {
        float ob = __shfl_xor_sync(0xFFFFFFFFu, best0, off);
        int   oi = __shfl_xor_sync(0xFFFFFFFFu, bi0,   off);
        float os = __shfl_xor_sync(0xFFFFFFFFu, sec0,  off);
        if (ob > best0 || (ob == best0 && oi < bi0)) {
            sec0 = fmaxf(fmaxf(sec0, os), best0); best0 = ob; bi0 = oi;
        } else sec0 = fmaxf(fmaxf(sec0, os), ob);
        ob = __shfl_xor_sync(0xFFFFFFFFu, best1, off);
        oi = __shfl_xor_sync(0xFFFFFFFFu, bi1,   off);
        os = __shfl_xor_sync(0xFFFFFFFFu, sec1,  off);
        if (ob > best1 || (ob == best1 && oi < bi1)) {
            sec1 = fmaxf(fmaxf(sec1, os), best1); best1 = ob; bi1 = oi;
        } else sec1 = fmaxf(fmaxf(sec1, os), ob);
    }

    if (c4 == 0) {
        int r0 = rb + warp * 16 + q;
        size_t s0 = (size_t)kseg * B_T + r0;
        g_pb[s0] = best0; g_ps[s0] = sec0; g_px[s0] = bi0;
        size_t s1 = s0 + 8;
        g_pb[s1] = best1; g_ps[s1] = sec1; g_px[s1] = bi1;
    }
}

// ============================================================================
// Kernel 4: merge KSP (best, second, idx) partials per row; clean rows write
// their label, near-ties go to the dirty list.
// second-of-union = max(second-largest of bests, max of seconds).
// ============================================================================
__global__ __launch_bounds__(256) void merge_kernel(float* __restrict__ out) {
    int row = blockIdx.x * 256 + threadIdx.x;
    if (row >= B_T) return;
    float B = __int_as_float(0xff800000), S = B;
    int I = 0;
#pragma unroll
    for (int s = 0; s < KSP; ++s) {
        float b = g_pb[(size_t)s * B_T + row];
        float sec = g_ps[(size_t)s * B_T + row];
        int   i = g_px[(size_t)s * B_T + row];
        if (b > B) { S = fmaxf(S, B); B = b; I = i; }   // ascending kseg => first-max
        else       { S = fmaxf(S, b); }
        S = fmaxf(S, sec);
    }
    if (B - S >= DELTA) out[row] = (float)I;
    else { int ix = atomicAdd(&g_dirty_n, 1); g_dirty[ix] = row; }
}

// ============================================================================
// Kernel 5: exact fp32 rescore of dirty rows, atomic-free, MLP-unrolled.
// ============================================================================
__device__ __forceinline__ unsigned long long mk_key(float v, uint32_t rk) {
    uint32_t u  = __float_as_uint(v);
    uint32_t ou = u ^ ((uint32_t)((int32_t)u >> 31) | 0x80000000u);
    return ((unsigned long long)ou << 32) | rk;
}
__global__ __launch_bounds__(256) void cleanup_kernel(const float* __restrict__ CB,
                                                      float* __restrict__ out) {
    __shared__ float vrow[E_DIM];
    __shared__ unsigned long long wred[8];
    const int n = g_dirty_n;
    for (int i = blockIdx.x; i < n; i += gridDim.x) {
        const int row = g_dirty[i];
        if (threadIdx.x < E_DIM) vrow[threadIdx.x] = g_V[(size_t)row * E_DIM + threadIdx.x];
        __syncthreads();
        float v[E_DIM];
#pragma unroll
        for (int e = 0; e < E_DIM; ++e) v[e] = vrow[e];

        unsigned long long best = 0ull;
#pragma unroll 4
        for (int c = threadIdx.x; c < K_CB; c += 256) {
            const float4* cb = (const float4*)(CB + (size_t)c * E_DIM);
            float4 a = cb[0], b = cb[1], cc = cb[2], d = cb[3];
            float t0 = a.x * v[0], t1 = a.y * v[1];
            t0 = fmaf(a.z, v[2],  t0); t1 = fmaf(a.w, v[3],  t1);
            t0 = fmaf(b.x, v[4],  t0); t1 = fmaf(b.y, v[5],  t1);
            t0 = fmaf(b.z, v[6],  t0); t1 = fmaf(b.w, v[7],  t1);
            t0 = fmaf(cc.x, v[8],  t0); t1 = fmaf(cc.y, v[9],  t1);
            t0 = fmaf(cc.z, v[10], t0); t1 = fmaf(cc.w, v[11], t1);
            t0 = fmaf(d.x, v[12], t0); t1 = fmaf(d.y, v[13], t1);
            t0 = fmaf(d.z, v[14], t0); t1 = fmaf(d.w, v[15], t1);
            unsigned long long key = mk_key(t0 + t1, (uint32_t)(8191 - c));
            if (key > best) best = key;
        }
#pragma unroll
        for (int off = 16; off >= 1; off >>= 1) {
            unsigned long long ob = __shfl_xor_sync(0xFFFFFFFFu, best, off);
            if (ob > best) best = ob;
        }
        if ((threadIdx.x & 31) == 0) wred[threadIdx.x >> 5] = best;
        __syncthreads();
        if (threadIdx.x == 0) {
            unsigned long long b = wred[0];
#pragma unroll
            for (int w = 1; w < 8; ++w) if (wred[w] > b) b = wred[w];
            out[row] = (float)(8191 - (int)(uint32_t)b);
        }
        __syncthreads();
    }
}

// ============================================================================
extern "C" void kernel_launch(void* const* d_in, const int* in_sizes, int n_in,
                              void* d_out, int out_size) {
    // Input dispatch by element count (ordering-proof):
    //   H = 5,120,000 ; P = 5,120 ; CB = 131,072
    const float* H  = nullptr;
    const float* P  = nullptr;
    const float* CB = nullptr;
    for (int i = 0; i < n_in; ++i) {
        if      (in_sizes[i] == B_T * D_IN)   H  = (const float*)d_in[i];
        else if (in_sizes[i] == D_IN * E_DIM) P  = (const float*)d_in[i];
        else if (in_sizes[i] == K_CB * E_DIM) CB = (const float*)d_in[i];
    }
    if (!H)  H  = (const float*)d_in[0];
    if (!P)  P  = (const float*)d_in[1];
    if (!CB) CB = (const float*)d_in[2];

    float* out = (float*)d_out;   // labels as float VALUES (float32 output buffer)

    proj_split_kernel<<<B_T / 8, 256>>>(H, P);
    cb_split_kernel<<<(K_CB + 255) / 256, 256>>>(CB);
    score_kernel<<<dim3(GRID_R, KSP), 256>>>();
    merge_kernel<<<(B_T + 255) / 256, 256>>>(out);
    cleanup_kernel<<<512, 256>>>(CB, out);
}